// round 5
// baseline (speedup 1.0000x reference)
#include <cuda_runtime.h>
#include <cuda_fp16.h>
#include <cstdint>
#include <cstddef>

#define MTOT 8192
#define KTOT 4096
#define NTOT 16384

#define BM 128
#define BN 256
#define BK 64                      // halves per k-chunk (128B)
#define STAGES 4
#define KIT (KTOT / BK)            // 64
#define ASTRIDE 144                // 128B row + 16B pad (conflict-free)
#define A_STAGE (128 * ASTRIDE)
#define B_STAGE (256 * ASTRIDE)
#define STG_B (A_STAGE + B_STAGE)  // 55296
#define SMEM_TOTAL (STAGES * STG_B) // 221184

// ---------------- scratch ----------------
__device__ __half g_xh[(size_t)MTOT * KTOT];   // 64 MB
__device__ __half g_wh[(size_t)NTOT * KTOT];   // 128 MB

// ---------------- PTX helpers ----------------
__device__ __forceinline__ uint32_t smem_u32(const void* p) {
    uint32_t a;
    asm("{ .reg .u64 t; cvta.to.shared.u64 t, %1; cvt.u32.u64 %0, t; }" : "=r"(a) : "l"(p));
    return a;
}
#define CP16(dst, src) \
    asm volatile("cp.async.cg.shared.global [%0], [%1], 16;" :: "r"(dst), "l"(src) : "memory")
#define CP_COMMIT() asm volatile("cp.async.commit_group;" ::: "memory")
#define CP_WAIT(n)  asm volatile("cp.async.wait_group %0;" :: "n"(n) : "memory")

__device__ __forceinline__ void ldsm_x4(uint32_t* r, uint32_t addr) {
    asm volatile("ldmatrix.sync.aligned.m8n8.x4.shared.b16 {%0,%1,%2,%3}, [%4];"
                 : "=r"(r[0]), "=r"(r[1]), "=r"(r[2]), "=r"(r[3]) : "r"(addr));
}
__device__ __forceinline__ void mma_f16(float* d, const uint32_t* a, const uint32_t* b) {
    asm volatile(
        "mma.sync.aligned.m16n8k16.row.col.f32.f16.f16.f32 "
        "{%0,%1,%2,%3}, {%4,%5,%6,%7}, {%8,%9}, {%0,%1,%2,%3};"
        : "+f"(d[0]), "+f"(d[1]), "+f"(d[2]), "+f"(d[3])
        : "r"(a[0]), "r"(a[1]), "r"(a[2]), "r"(a[3]), "r"(b[0]), "r"(b[1]));
}

// ---------------- kernel 1: x fp32 -> fp16 ----------------
__global__ void __launch_bounds__(256) cx_kernel(const float* __restrict__ x) {
    size_t idx = (size_t)blockIdx.x * 256 + threadIdx.x;
    const float4* xi = (const float4*)x;
    float4 v0 = xi[idx * 2];
    float4 v1 = xi[idx * 2 + 1];
    __half2 h[4];
    h[0] = __float22half2_rn(make_float2(v0.x, v0.y));
    h[1] = __float22half2_rn(make_float2(v0.z, v0.w));
    h[2] = __float22half2_rn(make_float2(v1.x, v1.y));
    h[3] = __float22half2_rn(make_float2(v1.z, v1.w));
    ((uint4*)g_xh)[idx] = *(uint4*)h;
}

// ---------------- kernel 2: W int32 -> fp16 (exact) ----------------
__global__ void __launch_bounds__(256) cw_kernel(const int* __restrict__ wq) {
    size_t idx = (size_t)blockIdx.x * 256 + threadIdx.x;
    const int4* wi = (const int4*)wq;
    int4 v0 = wi[idx * 2];
    int4 v1 = wi[idx * 2 + 1];
    __half h[8];
    h[0] = __int2half_rn(v0.x); h[1] = __int2half_rn(v0.y);
    h[2] = __int2half_rn(v0.z); h[3] = __int2half_rn(v0.w);
    h[4] = __int2half_rn(v1.x); h[5] = __int2half_rn(v1.y);
    h[6] = __int2half_rn(v1.z); h[7] = __int2half_rn(v1.w);
    ((uint4*)g_wh)[idx] = *(uint4*)h;
}

// ---------------- kernel 3: fp16 HMMA GEMM, 8 warps, warptile 64x64 ----------------
__global__ void __launch_bounds__(256, 1) gemm_kernel(
    float* __restrict__ out, const float* __restrict__ wscale,
    const float* __restrict__ bias)
{
    extern __shared__ uint8_t smem[];

    int tid = threadIdx.x;
    int wid = tid >> 5;
    int lane = tid & 31;
    int wm = wid >> 2;          // 0..1
    int wn = wid & 3;           // 0..3

    // GM=8 M-grouped raster over 64(m) x 64(n) tile grid
    int gid = blockIdx.x;
    int group = gid >> 9;
    int rem = gid & 511;
    int pid_m = group * 8 + (rem & 7);
    int pid_n = rem >> 3;

    const __half* Ab = g_xh + (size_t)pid_m * BM * KTOT;
    const __half* Bb = g_wh + (size_t)pid_n * BN * KTOT;

    uint32_t smem0 = smem_u32(smem);

    // cp.async: 3072 16B chunks per stage, 12 per thread
    auto issue = [&](int it) {
        uint32_t st = smem0 + (it % STAGES) * STG_B;
        int k0 = it * BK;
#pragma unroll
        for (int j = 0; j < 12; j++) {
            int c = tid + j * 256;
            if (c < 1024) {               // A: 128 rows x 8 chunks
                int row = c >> 3, col = c & 7;
                CP16(st + row * ASTRIDE + col * 16,
                     Ab + (size_t)row * KTOT + k0 + col * 8);
            } else {                      // B: 256 rows x 8 chunks
                int cc = c - 1024;
                int row = cc >> 3, col = cc & 7;
                CP16(st + A_STAGE + row * ASTRIDE + col * 16,
                     Bb + (size_t)row * KTOT + k0 + col * 8);
            }
        }
    };

#pragma unroll
    for (int s = 0; s < STAGES - 1; s++) {
        issue(s);
        CP_COMMIT();
    }

    float acc[4][8][4];
#pragma unroll
    for (int f = 0; f < 4; f++)
#pragma unroll
        for (int g = 0; g < 8; g++)
#pragma unroll
            for (int e = 0; e < 4; e++) acc[f][g][e] = 0.f;

    // ldmatrix lane addressing
    int j8 = lane >> 3;           // matrix id 0..3
    int r8 = lane & 7;
    // A x4: (m0-7,k0-7),(m8-15,k0-7),(m0-7,k8-15),(m8-15,k8-15)
    int a_row = wm * 64 + (j8 & 1) * 8 + r8;
    int a_koff = (j8 >> 1) * 16;
    // B x4: (n0-7,k0-7),(n0-7,k8-15),(n8-15,k0-7),(n8-15,k8-15)
    int b_row = wn * 64 + (j8 >> 1) * 8 + r8;
    int b_koff = (j8 & 1) * 16;

    for (int it = 0; it < KIT; it++) {
        CP_WAIT(STAGES - 2);
        __syncthreads();
        if (it + STAGES - 1 < KIT) issue(it + STAGES - 1);
        CP_COMMIT();

        uint32_t aB = smem0 + (it % STAGES) * STG_B;
        uint32_t bB = aB + A_STAGE;

#pragma unroll
        for (int ks = 0; ks < 4; ks++) {
            uint32_t a[4][4];
#pragma unroll
            for (int f = 0; f < 4; f++)
                ldsm_x4(a[f], aB + (a_row + f * 16) * ASTRIDE + ks * 32 + a_koff);
            uint32_t b[4][4];
#pragma unroll
            for (int gg = 0; gg < 4; gg++)
                ldsm_x4(b[gg], bB + (b_row + gg * 16) * ASTRIDE + ks * 32 + b_koff);
#pragma unroll
            for (int f = 0; f < 4; f++)
#pragma unroll
                for (int g = 0; g < 8; g++)
                    mma_f16(acc[f][g], a[f], b[g >> 1] + (g & 1) * 2);
        }
    }

    // ---------------- epilogue: dequant + bias ----------------
    int lr = lane >> 2;
    int lc2 = (lane & 3) * 2;
#pragma unroll
    for (int f = 0; f < 4; f++) {
        int gm = pid_m * BM + wm * 64 + f * 16 + lr;
        float* o0 = out + (size_t)gm * NTOT + pid_n * BN;
        float* o1 = o0 + (size_t)8 * NTOT;
#pragma unroll
        for (int g = 0; g < 8; g++) {
            int nc = wn * 64 + g * 8 + lc2;
            int gn = pid_n * BN + nc;
            float w0 = __ldg(wscale + gn), w1 = __ldg(wscale + gn + 1);
            float b0 = __ldg(bias + gn),   b1 = __ldg(bias + gn + 1);
            float2 r0, r1;
            r0.x = fmaf(acc[f][g][0], w0, b0);
            r0.y = fmaf(acc[f][g][1], w1, b1);
            r1.x = fmaf(acc[f][g][2], w0, b0);
            r1.y = fmaf(acc[f][g][3], w1, b1);
            *(float2*)(o0 + nc) = r0;
            *(float2*)(o1 + nc) = r1;
        }
    }
}

// ---------------- launch ----------------
extern "C" void kernel_launch(void* const* d_in, const int* in_sizes, int n_in,
                              void* d_out, int out_size) {
    const float* x      = (const float*)d_in[0];
    const int*   wq     = (const int*)d_in[1];
    const float* wscale = (const float*)d_in[2];
    const float* bias   = (const float*)d_in[3];
    float* out = (float*)d_out;

    cudaFuncSetAttribute(gemm_kernel, cudaFuncAttributeMaxDynamicSharedMemorySize, SMEM_TOTAL);

    cx_kernel<<<(int)((size_t)MTOT * KTOT / 8 / 256), 256>>>(x);
    cw_kernel<<<(int)((size_t)NTOT * KTOT / 8 / 256), 256>>>(wq);
    gemm_kernel<<<4096, 256, SMEM_TOTAL>>>(out, wscale, bias);
}

// round 6
// speedup vs baseline: 1.0669x; 1.0669x over previous
#include <cuda_runtime.h>
#include <cuda_fp16.h>
#include <cstdint>
#include <cstddef>

#define MTOT 8192
#define KTOT 4096
#define NTOT 16384

#define BM 128
#define BN 256
#define BK 64
#define STAGES 4
#define KIT (KTOT / BK)            // 64
#define ASTRIDE 144
#define A_STAGE (128 * ASTRIDE)
#define B_STAGE (256 * ASTRIDE)
#define STG_B (A_STAGE + B_STAGE)
#define SMEM_TOTAL (STAGES * STG_B)

// ---------------- scratch ----------------
__device__ __half g_xh[(size_t)MTOT * KTOT];
__device__ __half g_wh[(size_t)NTOT * KTOT];

// ---------------- PTX helpers ----------------
__device__ __forceinline__ uint32_t smem_u32(const void* p) {
    uint32_t a;
    asm("{ .reg .u64 t; cvta.to.shared.u64 t, %1; cvt.u32.u64 %0, t; }" : "=r"(a) : "l"(p));
    return a;
}
#define CP16(dst, src) \
    asm volatile("cp.async.cg.shared.global [%0], [%1], 16;" :: "r"(dst), "l"(src) : "memory")
#define CP_COMMIT() asm volatile("cp.async.commit_group;" ::: "memory")
#define CP_WAIT(n)  asm volatile("cp.async.wait_group %0;" :: "n"(n) : "memory")

__device__ __forceinline__ void ldsm_x4(uint32_t* r, uint32_t addr) {
    asm volatile("ldmatrix.sync.aligned.m8n8.x4.shared.b16 {%0,%1,%2,%3}, [%4];"
                 : "=r"(r[0]), "=r"(r[1]), "=r"(r[2]), "=r"(r[3]) : "r"(addr));
}
__device__ __forceinline__ void mma_f16(float* d, const uint32_t* a, const uint32_t* b) {
    asm volatile(
        "mma.sync.aligned.m16n8k16.row.col.f32.f16.f16.f32 "
        "{%0,%1,%2,%3}, {%4,%5,%6,%7}, {%8,%9}, {%0,%1,%2,%3};"
        : "+f"(d[0]), "+f"(d[1]), "+f"(d[2]), "+f"(d[3])
        : "r"(a[0]), "r"(a[1]), "r"(a[2]), "r"(a[3]), "r"(b[0]), "r"(b[1]));
}

// ---------------- kernel 1: x fp32 -> fp16 ----------------
__global__ void __launch_bounds__(256) cx_kernel(const float* __restrict__ x) {
    size_t idx = (size_t)blockIdx.x * 256 + threadIdx.x;
    const float4* xi = (const float4*)x;
    float4 v0 = xi[idx * 2];
    float4 v1 = xi[idx * 2 + 1];
    __half2 h[4];
    h[0] = __float22half2_rn(make_float2(v0.x, v0.y));
    h[1] = __float22half2_rn(make_float2(v0.z, v0.w));
    h[2] = __float22half2_rn(make_float2(v1.x, v1.y));
    h[3] = __float22half2_rn(make_float2(v1.z, v1.w));
    ((uint4*)g_xh)[idx] = *(uint4*)h;
}

// ---------------- kernel 2: W int32 -> fp16 (exact) ----------------
__global__ void __launch_bounds__(256) cw_kernel(const int* __restrict__ wq) {
    size_t idx = (size_t)blockIdx.x * 256 + threadIdx.x;
    const int4* wi = (const int4*)wq;
    int4 v0 = wi[idx * 2];
    int4 v1 = wi[idx * 2 + 1];
    __half h[8];
    h[0] = __int2half_rn(v0.x); h[1] = __int2half_rn(v0.y);
    h[2] = __int2half_rn(v0.z); h[3] = __int2half_rn(v0.w);
    h[4] = __int2half_rn(v1.x); h[5] = __int2half_rn(v1.y);
    h[6] = __int2half_rn(v1.z); h[7] = __int2half_rn(v1.w);
    ((uint4*)g_wh)[idx] = *(uint4*)h;
}

// ---------------- kernel 3: fp16 HMMA GEMM, 8 warps, 64x64, reg-dbuf frags ----------------
__global__ void __launch_bounds__(256, 1) gemm_kernel(
    float* __restrict__ out, const float* __restrict__ wscale,
    const float* __restrict__ bias)
{
    extern __shared__ uint8_t smem[];

    int tid = threadIdx.x;
    int wid = tid >> 5;
    int lane = tid & 31;
    int wm = wid >> 2;
    int wn = wid & 3;

    int gid = blockIdx.x;
    int group = gid >> 9;
    int rem = gid & 511;
    int pid_m = group * 8 + (rem & 7);
    int pid_n = rem >> 3;

    const __half* Ab = g_xh + (size_t)pid_m * BM * KTOT;
    const __half* Bb = g_wh + (size_t)pid_n * BN * KTOT;

    uint32_t smem0 = smem_u32(smem);

    auto issue = [&](int it) {
        uint32_t st = smem0 + (it % STAGES) * STG_B;
        int k0 = it * BK;
        const __half* Asrc = Ab + (size_t)(tid >> 3) * KTOT + k0 + (tid & 7) * 8;
        const __half* Bsrc = Bb + (size_t)(tid >> 3) * KTOT + k0 + (tid & 7) * 8;
        uint32_t Adst = st + (tid >> 3) * ASTRIDE + (tid & 7) * 16;
        uint32_t Bdst = st + A_STAGE + (tid >> 3) * ASTRIDE + (tid & 7) * 16;
#pragma unroll
        for (int j = 0; j < 4; j++)
            CP16(Adst + j * 32 * ASTRIDE, Asrc + (size_t)j * 32 * KTOT);
#pragma unroll
        for (int j = 0; j < 8; j++)
            CP16(Bdst + j * 32 * ASTRIDE, Bsrc + (size_t)j * 32 * KTOT);
    };

#pragma unroll
    for (int s = 0; s < STAGES - 1; s++) {
        issue(s);
        CP_COMMIT();
    }

    float acc[4][8][4];
#pragma unroll
    for (int f = 0; f < 4; f++)
#pragma unroll
        for (int g = 0; g < 8; g++)
#pragma unroll
            for (int e = 0; e < 4; e++) acc[f][g][e] = 0.f;

    int j8 = lane >> 3;
    int r8 = lane & 7;
    int a_row = wm * 64 + (j8 & 1) * 8 + r8;
    int a_koff = (j8 >> 1) * 16;
    int b_row = wn * 64 + (j8 >> 1) * 8 + r8;
    int b_koff = (j8 & 1) * 16;

    uint32_t a[2][4][4], b[2][4][4];

    // ldsm for a given stage base and ks into buffer slot
    auto ldfrags = [&](int slot, uint32_t aB, uint32_t bB, int ks) {
#pragma unroll
        for (int f = 0; f < 4; f++)
            ldsm_x4(a[slot][f], aB + (a_row + f * 16) * ASTRIDE + ks * 32 + a_koff);
#pragma unroll
        for (int gg = 0; gg < 4; gg++)
            ldsm_x4(b[slot][gg], bB + (b_row + gg * 16) * ASTRIDE + ks * 32 + b_koff);
    };

    // prologue: stage 0 ready, load ks=0 frags
    CP_WAIT(STAGES - 2);
    __syncthreads();
    {
        uint32_t aB = smem0;
        ldfrags(0, aB, aB + A_STAGE, 0);
    }

    int cur = 0;
    for (int it = 0; it < KIT; it++) {
        uint32_t aB = smem0 + (it % STAGES) * STG_B;
        uint32_t bB = aB + A_STAGE;

#pragma unroll
        for (int ks = 0; ks < 4; ks++) {
            int nxt = cur ^ 1;
            if (ks < 3) {
                ldfrags(nxt, aB, bB, ks + 1);
            } else if (it + 1 < KIT) {
                // stage transition: wait next stage, sync, refill, load its ks0
                CP_WAIT(STAGES - 2);
                __syncthreads();
                if (it + STAGES - 1 < KIT) issue(it + STAGES - 1);
                CP_COMMIT();
                uint32_t aB2 = smem0 + ((it + 1) % STAGES) * STG_B;
                ldfrags(nxt, aB2, aB2 + A_STAGE, 0);
            }
#pragma unroll
            for (int g = 0; g < 8; g++)
#pragma unroll
                for (int f = 0; f < 4; f++)
                    mma_f16(acc[f][g], a[cur][f], b[cur][g >> 1] + (g & 1) * 2);
            cur = nxt;
        }
    }

    // ---------------- epilogue ----------------
    int lr = lane >> 2;
    int lc2 = (lane & 3) * 2;
#pragma unroll
    for (int f = 0; f < 4; f++) {
        int gm = pid_m * BM + wm * 64 + f * 16 + lr;
        float* o0 = out + (size_t)gm * NTOT + pid_n * BN;
        float* o1 = o0 + (size_t)8 * NTOT;
#pragma unroll
        for (int g = 0; g < 8; g++) {
            int nc = wn * 64 + g * 8 + lc2;
            int gn = pid_n * BN + nc;
            float w0 = __ldg(wscale + gn), w1 = __ldg(wscale + gn + 1);
            float b0 = __ldg(bias + gn),   b1 = __ldg(bias + gn + 1);
            float2 r0, r1;
            r0.x = fmaf(acc[f][g][0], w0, b0);
            r0.y = fmaf(acc[f][g][1], w1, b1);
            r1.x = fmaf(acc[f][g][2], w0, b0);
            r1.y = fmaf(acc[f][g][3], w1, b1);
            *(float2*)(o0 + nc) = r0;
            *(float2*)(o1 + nc) = r1;
        }
    }
}

// ---------------- launch ----------------
extern "C" void kernel_launch(void* const* d_in, const int* in_sizes, int n_in,
                              void* d_out, int out_size) {
    const float* x      = (const float*)d_in[0];
    const int*   wq     = (const int*)d_in[1];
    const float* wscale = (const float*)d_in[2];
    const float* bias   = (const float*)d_in[3];
    float* out = (float*)d_out;

    cudaFuncSetAttribute(gemm_kernel, cudaFuncAttributeMaxDynamicSharedMemorySize, SMEM_TOTAL);

    cx_kernel<<<(int)((size_t)MTOT * KTOT / 8 / 256), 256>>>(x);
    cw_kernel<<<(int)((size_t)NTOT * KTOT / 8 / 256), 256>>>(wq);
    gemm_kernel<<<4096, 256, SMEM_TOTAL>>>(out, wscale, bias);
}